// round 12
// baseline (speedup 1.0000x reference)
#include <cuda_runtime.h>
#include <cuda_bf16.h>
#include <math.h>
#include <stddef.h>

// Dims
#define NSEQ 512      // nodes (= GRU sequence length)
#define BT   64       // batch
#define CIND 128
#define HD   256
#define G3   768      // 3*HD
#define ED   8192     // edges
#define OUTD 12
#define ROWS (NSEQ*BT)  // 32768

#define NCTA_SCAN 128   // persistent scan CTAs (32 k-blocks x 4 b-blocks)

// ---------------- static device scratch (no runtime allocation) -------------
__device__ float g_xs [NSEQ*BT*CIND];     // [n][b][c]
__device__ float g_agg[BT*NSEQ*CIND];     // [b][n][c]
__device__ float g_gi0[NSEQ*BT*G3];
__device__ float g_gi1[NSEQ*BT*G3];
__device__ float g_h1 [NSEQ*BT*HD];
__device__ float g_h2 [NSEQ*BT*HD];
__device__ float g_cz [ROWS*HD];
__device__ float g_ch [ROWS*HD];
__device__ float g_Z  [ROWS*HD];
__device__ float g_Hn [ROWS*HD];
__device__ float g_WT0[CIND*G3];          // Wih0^T  [128][768]
__device__ float g_WT1[HD*G3];            // Wih1^T  [256][768]

__device__ int      g_count[513];
__device__ int      g_rowstart[513];
__device__ int      g_fill[512];
__device__ int      g_eidx[ED];
__device__ int      g_srcs[ED];
__device__ float    g_normv[ED];
__device__ float    g_dinv[512];
__device__ float    g_selfn[512];
__device__ unsigned g_bar0;
__device__ unsigned g_bar1;

// ---------------- CSR build (deterministic) ---------------------------------
__global__ void k_zero() {
    int i = blockIdx.x * 256 + threadIdx.x;
    if (i < 513) g_count[i] = 0;
    if (i < 512) g_fill[i] = 0;
    if (i == 0) { g_bar0 = 0u; g_bar1 = 0u; }
}

__global__ void k_count(const int* __restrict__ ei) {
    int e = blockIdx.x * 256 + threadIdx.x;
    if (e < ED) atomicAdd(&g_count[ei[ED + e]], 1);
}

__global__ void k_scan() {
    if (threadIdx.x == 0) {
        int s = 0;
        for (int i = 0; i < 512; i++) { g_rowstart[i] = s; s += g_count[i]; }
        g_rowstart[512] = s;
    }
}

__global__ void k_fill(const int* __restrict__ ei) {
    int e = blockIdx.x * 256 + threadIdx.x;
    if (e < ED) {
        int t = ei[ED + e];
        int pos = g_rowstart[t] + atomicAdd(&g_fill[t], 1);
        g_eidx[pos] = e;
    }
}

// sort each row's edge ids ascending (removes fill nondeterminism), then
// sequential degree sum -> deterministic float results.
__global__ void k_sortdeg(const float* __restrict__ ew) {
    int t = blockIdx.x * 256 + threadIdx.x;
    if (t < 512) {
        int rs = g_rowstart[t], re = g_rowstart[t + 1];
        for (int i = rs + 1; i < re; i++) {
            int key = g_eidx[i];
            int j = i - 1;
            while (j >= rs && g_eidx[j] > key) { g_eidx[j + 1] = g_eidx[j]; j--; }
            g_eidx[j + 1] = key;
        }
        float d = 2.0f;                      // improved=True self-loop weight
        for (int s = rs; s < re; s++) d += ew[g_eidx[s]];
        float di = rsqrtf(d);
        g_dinv[t] = di;
        g_selfn[t] = 2.0f * di * di;
    }
}

__global__ void k_norm(const int* __restrict__ ei, const float* __restrict__ ew) {
    int s = blockIdx.x * 256 + threadIdx.x;
    if (s < ED) {
        int e = g_eidx[s];
        int src = ei[e], tgt = ei[ED + e];
        g_srcs[s] = src;
        g_normv[s] = g_dinv[src] * ew[e] * g_dinv[tgt];
    }
}

// ---------------- aggregation + transposes ----------------------------------
__global__ void k_agg(const float* __restrict__ x, float* __restrict__ agg) {
    int c = threadIdx.x;          // 0..127
    int t = blockIdx.x;           // node
    int b = blockIdx.y;           // batch
    int rs = g_rowstart[t], re = g_rowstart[t + 1];
    float v = g_selfn[t] * x[((size_t)b * NSEQ + t) * CIND + c];
    for (int s = rs; s < re; s++)
        v += g_normv[s] * x[((size_t)b * NSEQ + g_srcs[s]) * CIND + c];
    agg[((size_t)b * NSEQ + t) * CIND + c] = v;
}

__global__ void k_xs(const float* __restrict__ x, float* __restrict__ xs) {
    int c = threadIdx.x;
    int n = blockIdx.x, b = blockIdx.y;
    xs[((size_t)n * BT + b) * CIND + c] = x[((size_t)b * NSEQ + n) * CIND + c];
}

// W[R][C] -> WT[C][R]
__global__ void k_transpose(const float* __restrict__ W, float* __restrict__ WT,
                            int R, int C) {
    int i = blockIdx.x * 256 + threadIdx.x;
    if (i < R * C) {
        int r = i / C, c = i % C;
        WT[(size_t)c * R + r] = W[i];
    }
}

// ---------------- GEMM 128x128x16, 8x8 microtile, fused epilogue ------------
// mode: 0 = bias only, 1 = sigmoid(v+b), 3 = (1-Z)*tanh(v+b)
__global__ void __launch_bounds__(256)
gemm128(const float* __restrict__ A, const float* __restrict__ B,
        const float* __restrict__ bias, float* __restrict__ C,
        int N, int K, int mode, const float* __restrict__ zbuf)
{
    __shared__ float As[16 * 132];
    __shared__ float Bs[16 * 128];
    int tid = threadIdx.x;
    int row0 = blockIdx.y * 128, col0 = blockIdx.x * 128;
    int tx = tid & 15, ty = tid >> 4;
    float acc[8][8];
#pragma unroll
    for (int i = 0; i < 8; i++)
#pragma unroll
        for (int j = 0; j < 8; j++) acc[i][j] = 0.f;

    for (int kt = 0; kt < K; kt += 16) {
#pragma unroll
        for (int q = 0; q < 2; q++) {
            int p = tid * 2 + q;             // 0..511 (float4 idx)
            int ar = p >> 2;                 // row in tile
            int ac = (p & 3) * 4;            // k within tile
            float4 v = *(const float4*)&A[(size_t)(row0 + ar) * K + kt + ac];
            As[(ac + 0) * 132 + ar] = v.x;
            As[(ac + 1) * 132 + ar] = v.y;
            As[(ac + 2) * 132 + ar] = v.z;
            As[(ac + 3) * 132 + ar] = v.w;
        }
#pragma unroll
        for (int q = 0; q < 2; q++) {
            int p = tid * 2 + q;
            int br = p >> 5;                 // 0..15
            int bc = (p & 31) * 4;
            *(float4*)&Bs[br * 128 + bc] =
                *(const float4*)&B[(size_t)(kt + br) * N + col0 + bc];
        }
        __syncthreads();
#pragma unroll
        for (int kk = 0; kk < 16; kk++) {
            float a[8], b[8];
            *(float4*)&a[0] = *(float4*)&As[kk * 132 + ty * 8];
            *(float4*)&a[4] = *(float4*)&As[kk * 132 + ty * 8 + 4];
            *(float4*)&b[0] = *(float4*)&Bs[kk * 128 + tx * 8];
            *(float4*)&b[4] = *(float4*)&Bs[kk * 128 + tx * 8 + 4];
#pragma unroll
            for (int i = 0; i < 8; i++)
#pragma unroll
                for (int j = 0; j < 8; j++) acc[i][j] += a[i] * b[j];
        }
        __syncthreads();
    }

    int cbase = col0 + tx * 8;
    float bsv[8];
#pragma unroll
    for (int j = 0; j < 8; j++) bsv[j] = bias[cbase + j];
#pragma unroll
    for (int i = 0; i < 8; i++) {
        size_t roff = (size_t)(row0 + ty * 8 + i) * N + cbase;
        float o[8];
#pragma unroll
        for (int j = 0; j < 8; j++) {
            float v = acc[i][j] + bsv[j];
            if (mode == 1)      v = 1.0f / (1.0f + expf(-v));
            else if (mode == 3) { float z = zbuf[roff + j]; v = (1.0f - z) * tanhf(v); }
            o[j] = v;
        }
        *(float4*)&C[roff]     = *(float4*)&o[0];
        *(float4*)&C[roff + 4] = *(float4*)&o[4];
    }
}

// ---------------- persistent GRU layer scan ----------------------------------
// Grid (32, 4) = 128 CTAs (all co-resident on 148 SMs -> no deadlock risk).
//   blockIdx.x = k-block (8 hidden units), blockIdx.y = b-block (16 batches).
// Block: 128 threads, thread = (bl = tid&15, kl = tid>>4). One (b,k) pair per
// thread, all 3 gates. Whh rows for the k-block live in smem, loaded ONCE.
// h passes between steps through L2 (__stcg/__ldcg; per-launch L1 is
// incoherent across SMs). Grid barrier: monotonic counter, zeroed by k_zero
// at the start of each launch sequence -> deterministic across graph replays.
__global__ void __launch_bounds__(128, 1)
gru_scan(float* __restrict__ h_all, const float* __restrict__ gi,
         const float* __restrict__ Whh, const float* __restrict__ bhh,
         unsigned* __restrict__ bar)
{
    __shared__ float ws[8 * 3 * 256];     // [kl][gate][j] = 24 KB
    const int tid = threadIdx.x;
    const int bl  = tid & 15;
    const int kl  = tid >> 4;
    const int k   = blockIdx.x * 8 + kl;   // 0..255
    const int b   = blockIdx.y * 16 + bl;  // 0..63

    // Preload Whh rows (r: row k, z: row 256+k, n: row 512+k) for this k-block.
    for (int i = tid; i < 8 * 3 * 256; i += 128) {
        int j  = i & 255;
        int rg = i >> 8;           // 0..23
        int kk = rg / 3, g = rg % 3;
        ws[i] = Whh[((size_t)g * HD + blockIdx.x * 8 + kk) * HD + j];
    }
    __syncthreads();

    const float br_ = bhh[k], bz_ = bhh[HD + k], bn_ = bhh[2 * HD + k];
    const float* wr = &ws[(kl * 3 + 0) * 256];
    const float* wz = &ws[(kl * 3 + 1) * 256];
    const float* wn = &ws[(kl * 3 + 2) * 256];

    for (int t = 0; t < NSEQ; t++) {
        float accr = 0.f, accz = 0.f, accn = 0.f, hprev = 0.f;
        if (t > 0) {
            const float4* hp = (const float4*)(h_all + ((size_t)(t - 1) * BT + b) * HD);
            float4 vr = {0,0,0,0}, vz = {0,0,0,0}, vn = {0,0,0,0};
#pragma unroll 16
            for (int i = 0; i < 64; i++) {
                float4 hv = __ldcg(hp + i);
                float4 w1 = *(const float4*)&wr[i * 4];
                float4 w2 = *(const float4*)&wz[i * 4];
                float4 w3 = *(const float4*)&wn[i * 4];
                vr.x += hv.x * w1.x; vr.y += hv.y * w1.y;
                vr.z += hv.z * w1.z; vr.w += hv.w * w1.w;
                vz.x += hv.x * w2.x; vz.y += hv.y * w2.y;
                vz.z += hv.z * w2.z; vz.w += hv.w * w2.w;
                vn.x += hv.x * w3.x; vn.y += hv.y * w3.y;
                vn.z += hv.z * w3.z; vn.w += hv.w * w3.w;
            }
            accr = (vr.x + vr.y) + (vr.z + vr.w);
            accz = (vz.x + vz.y) + (vz.z + vz.w);
            accn = (vn.x + vn.y) + (vn.z + vn.w);
            hprev = __ldcg(&h_all[((size_t)(t - 1) * BT + b) * HD + k]);
        }

        size_t gbase = ((size_t)t * BT + b) * G3;
        float gr = __ldg(&gi[gbase + k]);
        float gz = __ldg(&gi[gbase + HD + k]);
        float gn = __ldg(&gi[gbase + 2 * HD + k]);

        float r = 1.0f / (1.0f + expf(-(gr + br_ + accr)));
        float z = 1.0f / (1.0f + expf(-(gz + bz_ + accz)));
        float n = tanhf(gn + bn_ + r * accn);
        float hn = (1.0f - z) * n + z * hprev;

        __stcg(&h_all[((size_t)t * BT + b) * HD + k], hn);

        // ---- grid barrier (release h[t], acquire before reading at t+1) ----
        __threadfence();          // order h store before the arrive
        __syncthreads();          // all threads of CTA have stored
        if (tid == 0) {
            atomicAdd(bar, 1u);
            unsigned target = (unsigned)NCTA_SCAN * (unsigned)(t + 1);
            volatile unsigned* vb = bar;
            while (*vb < target) __nanosleep(20);
            __threadfence();      // acquire
        }
        __syncthreads();          // release the CTA into step t+1
    }
}

// ---------------- fused heads + output --------------------------------------
__global__ void __launch_bounds__(256)
k_head(const float* __restrict__ h2, const float* __restrict__ Hn,
       const float* __restrict__ l1W, const float* __restrict__ l1b,
       const float* __restrict__ l2W, const float* __restrict__ l2b,
       const float* __restrict__ l3W, const float* __restrict__ l3b,
       float* __restrict__ out)
{
    int w = threadIdx.x >> 5, lane = threadIdx.x & 31;
    int r = blockIdx.x * 8 + w;              // row = b*512 + n
    int b = r >> 9, n = r & 511;
    const float* h2row = h2 + ((size_t)n * BT + b) * HD;
    const float* hnrow = Hn + (size_t)r * HD;
    float s1 = 0.f, s2 = 0.f;
#pragma unroll
    for (int j = 0; j < 8; j++) {
        int kk = lane + j * 32;
        s2 += h2row[kk] * l2W[kk];
        float hv = hnrow[kk];
        s1 += fmaxf(hv, 0.f) * l1W[kk];
    }
#pragma unroll
    for (int o = 16; o > 0; o >>= 1) {
        s1 += __shfl_xor_sync(0xFFFFFFFFu, s1, o);
        s2 += __shfl_xor_sync(0xFFFFFFFFu, s2, o);
    }
    float g  = s2 + l2b[0];
    float hh = s1 + l1b[0];
    if (lane < OUTD)
        out[(size_t)r * OUTD + lane] = g * l3W[lane] + hh * l3W[OUTD + lane] + l3b[lane];
}

// ---------------- host orchestration ----------------------------------------
extern "C" void kernel_launch(void* const* d_in, const int* in_sizes, int n_in,
                              void* d_out, int out_size)
{
    (void)in_sizes; (void)n_in; (void)out_size;

    const float* x    = (const float*)d_in[0];
    const int*   ei   = (const int*)  d_in[1];
    const float* ew   = (const float*)d_in[2];
    const float* Wz   = (const float*)d_in[3];
    const float* bz   = (const float*)d_in[4];
    const float* lzW  = (const float*)d_in[5];
    const float* lzb  = (const float*)d_in[6];
    // d_in[7..10] = Wr, br, lr_W, lr_b : dead (Hst = 0 kills the R branch)
    const float* Wh   = (const float*)d_in[11];
    const float* bh   = (const float*)d_in[12];
    const float* lhW  = (const float*)d_in[13];
    const float* lhb  = (const float*)d_in[14];
    const float* Wih0 = (const float*)d_in[15];
    const float* Whh0 = (const float*)d_in[16];
    const float* bih0 = (const float*)d_in[17];
    const float* bhh0 = (const float*)d_in[18];
    const float* Wih1 = (const float*)d_in[19];
    const float* Whh1 = (const float*)d_in[20];
    const float* bih1 = (const float*)d_in[21];
    const float* bhh1 = (const float*)d_in[22];
    const float* l1W  = (const float*)d_in[23];
    const float* l1b  = (const float*)d_in[24];
    const float* l2W  = (const float*)d_in[25];
    const float* l2b  = (const float*)d_in[26];
    const float* l3W  = (const float*)d_in[27];
    const float* l3b  = (const float*)d_in[28];
    float* out = (float*)d_out;

    void *p_xs, *p_agg, *p_gi0, *p_gi1, *p_h1, *p_h2,
         *p_cz, *p_ch, *p_Z, *p_Hn, *p_WT0, *p_WT1, *p_b0, *p_b1;
    cudaGetSymbolAddress(&p_xs,  g_xs);
    cudaGetSymbolAddress(&p_agg, g_agg);
    cudaGetSymbolAddress(&p_gi0, g_gi0);
    cudaGetSymbolAddress(&p_gi1, g_gi1);
    cudaGetSymbolAddress(&p_h1,  g_h1);
    cudaGetSymbolAddress(&p_h2,  g_h2);
    cudaGetSymbolAddress(&p_cz,  g_cz);
    cudaGetSymbolAddress(&p_ch,  g_ch);
    cudaGetSymbolAddress(&p_Z,   g_Z);
    cudaGetSymbolAddress(&p_Hn,  g_Hn);
    cudaGetSymbolAddress(&p_WT0, g_WT0);
    cudaGetSymbolAddress(&p_WT1, g_WT1);
    cudaGetSymbolAddress(&p_b0,  g_bar0);
    cudaGetSymbolAddress(&p_b1,  g_bar1);

    // ---- graph structure (deterministic CSR; zero float atomics) ----
    k_zero<<<3, 256>>>();
    k_count<<<32, 256>>>(ei);
    k_scan<<<1, 32>>>();
    k_fill<<<32, 256>>>(ei);
    k_sortdeg<<<2, 256>>>(ew);
    k_norm<<<32, 256>>>(ei, ew);

    // ---- layout prep ----
    k_xs<<<dim3(NSEQ, BT), CIND>>>(x, (float*)p_xs);
    k_transpose<<<(G3 * CIND + 255) / 256, 256>>>(Wih0, (float*)p_WT0, G3, CIND);
    k_transpose<<<(G3 * HD + 255) / 256, 256>>>(Wih1, (float*)p_WT1, G3, HD);
    k_agg<<<dim3(NSEQ, BT), CIND>>>(x, (float*)p_agg);

    // ---- parallel GEMMs ----
    // gi0 = xs @ Wih0^T + bih0   [32768,128] x [128,768]
    gemm128<<<dim3(G3 / 128, ROWS / 128), 256>>>(
        (const float*)p_xs, (const float*)p_WT0, bih0, (float*)p_gi0,
        G3, CIND, 0, nullptr);
    // cz = agg @ Wz + bz ; ch = agg @ Wh + bh     (A(XW) = (AX)W)
    gemm128<<<dim3(HD / 128, ROWS / 128), 256>>>(
        (const float*)p_agg, Wz, bz, (float*)p_cz, HD, CIND, 0, nullptr);
    gemm128<<<dim3(HD / 128, ROWS / 128), 256>>>(
        (const float*)p_agg, Wh, bh, (float*)p_ch, HD, CIND, 0, nullptr);
    // Z = sigmoid(cz @ lzW[0:256] + lzb)
    gemm128<<<dim3(HD / 128, ROWS / 128), 256>>>(
        (const float*)p_cz, lzW, lzb, (float*)p_Z, HD, HD, 1, nullptr);
    // Hn = (1-Z) * tanh(ch @ lhW[0:256] + lhb)
    gemm128<<<dim3(HD / 128, ROWS / 128), 256>>>(
        (const float*)p_ch, lhW, lhb, (float*)p_Hn, HD, HD, 3, (const float*)p_Z);

    // ---- GRU layer 0 scan (single persistent kernel, 512 steps) ----
    gru_scan<<<dim3(32, 4), 128>>>((float*)p_h1, (const float*)p_gi0,
                                   Whh0, bhh0, (unsigned*)p_b0);

    // gi1 = h1 @ Wih1^T + bih1   [32768,256] x [256,768]
    gemm128<<<dim3(G3 / 128, ROWS / 128), 256>>>(
        (const float*)p_h1, (const float*)p_WT1, bih1, (float*)p_gi1,
        G3, HD, 0, nullptr);

    // ---- GRU layer 1 scan ----
    gru_scan<<<dim3(32, 4), 128>>>((float*)p_h2, (const float*)p_gi1,
                                   Whh1, bhh1, (unsigned*)p_b1);

    // ---- fused heads -> out ----
    k_head<<<ROWS / 8, 256>>>((const float*)p_h2, (const float*)p_Hn,
                              l1W, l1b, l2W, l2b, l3W, l3b, out);
}

// round 15
// speedup vs baseline: 1.8944x; 1.8944x over previous
#include <cuda_runtime.h>
#include <cuda_bf16.h>
#include <math.h>
#include <stddef.h>

// Dims
#define NSEQ 512      // nodes (= GRU sequence length)
#define BT   64       // batch
#define CIND 128
#define HD   256
#define G3   768      // 3*HD
#define ED   8192     // edges
#define OUTD 12
#define ROWS (NSEQ*BT)  // 32768

#define NCTA_SCAN 128   // persistent scan CTAs (32 k-blocks x 4 b-blocks)

// ---------------- static device scratch (no runtime allocation) -------------
__device__ float g_xs [NSEQ*BT*CIND];     // [n][b][c]
__device__ float g_agg[BT*NSEQ*CIND];     // [b][n][c]
__device__ float g_gi0[NSEQ*BT*G3];
__device__ float g_gi1[NSEQ*BT*G3];
__device__ float g_h1 [NSEQ*BT*HD];
__device__ float g_h2 [NSEQ*BT*HD];
__device__ float g_cz [ROWS*HD];
__device__ float g_ch [ROWS*HD];
__device__ float g_Z  [ROWS*HD];
__device__ float g_Hn [ROWS*HD];
__device__ float g_WT0[CIND*G3];          // Wih0^T  [128][768]
__device__ float g_WT1[HD*G3];            // Wih1^T  [256][768]

__device__ int      g_count[513];
__device__ int      g_rowstart[513];
__device__ int      g_fill[512];
__device__ int      g_eidx[ED];
__device__ int      g_srcs[ED];
__device__ float    g_normv[ED];
__device__ float    g_dinv[512];
__device__ float    g_selfn[512];
__device__ unsigned g_bar0;
__device__ unsigned g_bar1;

// ---------------- CSR build (deterministic) ---------------------------------
__global__ void k_zero() {
    int i = blockIdx.x * 256 + threadIdx.x;
    if (i < 513) g_count[i] = 0;
    if (i < 512) g_fill[i] = 0;
    if (i == 0) { g_bar0 = 0u; g_bar1 = 0u; }
}

__global__ void k_count(const int* __restrict__ ei) {
    int e = blockIdx.x * 256 + threadIdx.x;
    if (e < ED) atomicAdd(&g_count[ei[ED + e]], 1);
}

__global__ void k_scan() {
    if (threadIdx.x == 0) {
        int s = 0;
        for (int i = 0; i < 512; i++) { g_rowstart[i] = s; s += g_count[i]; }
        g_rowstart[512] = s;
    }
}

__global__ void k_fill(const int* __restrict__ ei) {
    int e = blockIdx.x * 256 + threadIdx.x;
    if (e < ED) {
        int t = ei[ED + e];
        int pos = g_rowstart[t] + atomicAdd(&g_fill[t], 1);
        g_eidx[pos] = e;
    }
}

// sort each row's edge ids ascending (removes fill nondeterminism), then
// sequential degree sum -> deterministic float results.
__global__ void k_sortdeg(const float* __restrict__ ew) {
    int t = blockIdx.x * 256 + threadIdx.x;
    if (t < 512) {
        int rs = g_rowstart[t], re = g_rowstart[t + 1];
        for (int i = rs + 1; i < re; i++) {
            int key = g_eidx[i];
            int j = i - 1;
            while (j >= rs && g_eidx[j] > key) { g_eidx[j + 1] = g_eidx[j]; j--; }
            g_eidx[j + 1] = key;
        }
        float d = 2.0f;                      // improved=True self-loop weight
        for (int s = rs; s < re; s++) d += ew[g_eidx[s]];
        float di = rsqrtf(d);
        g_dinv[t] = di;
        g_selfn[t] = 2.0f * di * di;
    }
}

__global__ void k_norm(const int* __restrict__ ei, const float* __restrict__ ew) {
    int s = blockIdx.x * 256 + threadIdx.x;
    if (s < ED) {
        int e = g_eidx[s];
        int src = ei[e], tgt = ei[ED + e];
        g_srcs[s] = src;
        g_normv[s] = g_dinv[src] * ew[e] * g_dinv[tgt];
    }
}

// ---------------- aggregation + transposes ----------------------------------
__global__ void k_agg(const float* __restrict__ x, float* __restrict__ agg) {
    int c = threadIdx.x;          // 0..127
    int t = blockIdx.x;           // node
    int b = blockIdx.y;           // batch
    int rs = g_rowstart[t], re = g_rowstart[t + 1];
    float v = g_selfn[t] * x[((size_t)b * NSEQ + t) * CIND + c];
    for (int s = rs; s < re; s++)
        v += g_normv[s] * x[((size_t)b * NSEQ + g_srcs[s]) * CIND + c];
    agg[((size_t)b * NSEQ + t) * CIND + c] = v;
}

__global__ void k_xs(const float* __restrict__ x, float* __restrict__ xs) {
    int c = threadIdx.x;
    int n = blockIdx.x, b = blockIdx.y;
    xs[((size_t)n * BT + b) * CIND + c] = x[((size_t)b * NSEQ + n) * CIND + c];
}

// W[R][C] -> WT[C][R]
__global__ void k_transpose(const float* __restrict__ W, float* __restrict__ WT,
                            int R, int C) {
    int i = blockIdx.x * 256 + threadIdx.x;
    if (i < R * C) {
        int r = i / C, c = i % C;
        WT[(size_t)c * R + r] = W[i];
    }
}

// ---------------- GEMM 128x128x16, 8x8 microtile, fused epilogue ------------
// mode: 0 = bias only, 1 = sigmoid(v+b), 3 = (1-Z)*tanh(v+b)
__global__ void __launch_bounds__(256)
gemm128(const float* __restrict__ A, const float* __restrict__ B,
        const float* __restrict__ bias, float* __restrict__ C,
        int N, int K, int mode, const float* __restrict__ zbuf)
{
    __shared__ float As[16 * 132];
    __shared__ float Bs[16 * 128];
    int tid = threadIdx.x;
    int row0 = blockIdx.y * 128, col0 = blockIdx.x * 128;
    int tx = tid & 15, ty = tid >> 4;
    float acc[8][8];
#pragma unroll
    for (int i = 0; i < 8; i++)
#pragma unroll
        for (int j = 0; j < 8; j++) acc[i][j] = 0.f;

    for (int kt = 0; kt < K; kt += 16) {
#pragma unroll
        for (int q = 0; q < 2; q++) {
            int p = tid * 2 + q;             // 0..511 (float4 idx)
            int ar = p >> 2;                 // row in tile
            int ac = (p & 3) * 4;            // k within tile
            float4 v = *(const float4*)&A[(size_t)(row0 + ar) * K + kt + ac];
            As[(ac + 0) * 132 + ar] = v.x;
            As[(ac + 1) * 132 + ar] = v.y;
            As[(ac + 2) * 132 + ar] = v.z;
            As[(ac + 3) * 132 + ar] = v.w;
        }
#pragma unroll
        for (int q = 0; q < 2; q++) {
            int p = tid * 2 + q;
            int br = p >> 5;                 // 0..15
            int bc = (p & 31) * 4;
            *(float4*)&Bs[br * 128 + bc] =
                *(const float4*)&B[(size_t)(kt + br) * N + col0 + bc];
        }
        __syncthreads();
#pragma unroll
        for (int kk = 0; kk < 16; kk++) {
            float a[8], b[8];
            *(float4*)&a[0] = *(float4*)&As[kk * 132 + ty * 8];
            *(float4*)&a[4] = *(float4*)&As[kk * 132 + ty * 8 + 4];
            *(float4*)&b[0] = *(float4*)&Bs[kk * 128 + tx * 8];
            *(float4*)&b[4] = *(float4*)&Bs[kk * 128 + tx * 8 + 4];
#pragma unroll
            for (int i = 0; i < 8; i++)
#pragma unroll
                for (int j = 0; j < 8; j++) acc[i][j] += a[i] * b[j];
        }
        __syncthreads();
    }

    int cbase = col0 + tx * 8;
    float bsv[8];
#pragma unroll
    for (int j = 0; j < 8; j++) bsv[j] = bias[cbase + j];
#pragma unroll
    for (int i = 0; i < 8; i++) {
        size_t roff = (size_t)(row0 + ty * 8 + i) * N + cbase;
        float o[8];
#pragma unroll
        for (int j = 0; j < 8; j++) {
            float v = acc[i][j] + bsv[j];
            if (mode == 1)      v = 1.0f / (1.0f + expf(-v));
            else if (mode == 3) { float z = zbuf[roff + j]; v = (1.0f - z) * tanhf(v); }
            o[j] = v;
        }
        *(float4*)&C[roff]     = *(float4*)&o[0];
        *(float4*)&C[roff + 4] = *(float4*)&o[4];
    }
}

// ---------------- persistent GRU layer scan ----------------------------------
// Grid (32, 4) = 128 CTAs, 128 threads, 41 KB static smem -> guaranteed
// 1 CTA/SM and all 128 co-resident in wave 1 (no deadlock).
//   blockIdx.x = k-block (8 hidden units), blockIdx.y = b-block (16 batches).
//   thread = (bl = tid&15, kl = tid>>4): one (b,k) pair, all 3 gates.
// Per step: h[t-1] for the CTA's 16 batches is staged COOPERATIVELY into smem
// (16 KB, one copy -> 2 MB/step chip-wide L2 traffic, 8x less than before),
// then the 768-MAC/thread dot runs entirely from smem. gi[t] is prefetched
// before the barrier wait so its latency hides in the bubble. Whh lives in
// smem for the whole kernel. h passes between steps through L2 (stcg/ldcg).
// Grid barrier: monotonic counter (zeroed by k_zero each replay), release =
// threadfence+atomicAdd, acquire = tid0 volatile spin (no nanosleep).
__global__ void __launch_bounds__(128, 1)
gru_scan(float* __restrict__ h_all, const float* __restrict__ gi,
         const float* __restrict__ Whh, const float* __restrict__ bhh,
         unsigned* __restrict__ bar)
{
    __shared__ float ws[8 * 3 * 256];     // 24 KB weights for this k-block
    __shared__ float hs[16 * 260];        // 16.6 KB staged h (pitch 260)
    const int tid = threadIdx.x;
    const int bl  = tid & 15;
    const int kl  = tid >> 4;
    const int k   = blockIdx.x * 8 + kl;   // 0..255
    const int b   = blockIdx.y * 16 + bl;  // 0..63

    // Preload Whh rows (r: row k, z: row 256+k, n: row 512+k) for this k-block.
    for (int i = tid; i < 8 * 3 * 256; i += 128) {
        int j  = i & 255;
        int rg = i >> 8;           // 0..23 = kk*3+g
        int kk = rg / 3, g = rg % 3;
        ws[i] = Whh[((size_t)g * HD + blockIdx.x * 8 + kk) * HD + j];
    }
    __syncthreads();

    const float br_ = bhh[k], bz_ = bhh[HD + k], bn_ = bhh[2 * HD + k];
    const float* wr = &ws[(kl * 3 + 0) * 256];
    const float* wz = &ws[(kl * 3 + 1) * 256];
    const float* wn = &ws[(kl * 3 + 2) * 256];

    for (int t = 0; t < NSEQ; t++) {
        // ---- prefetch gi[t] (independent of the barrier) ----
        size_t gbase = ((size_t)t * BT + b) * G3;
        float gr = __ldg(&gi[gbase + k]);
        float gz = __ldg(&gi[gbase + HD + k]);
        float gn = __ldg(&gi[gbase + 2 * HD + k]);

        float accr = 0.f, accz = 0.f, accn = 0.f, hprev = 0.f;
        if (t > 0) {
            // ---- acquire: wait until all CTAs stored h[t-1] ----
            if (tid == 0) {
                unsigned target = (unsigned)NCTA_SCAN * (unsigned)t;
                volatile unsigned* vb = bar;
                while (*vb < target) { }
                __threadfence();
            }
            __syncthreads();

            // ---- stage h[t-1] for our 16 batches into smem (coalesced) ----
            const float4* hp = (const float4*)(h_all +
                ((size_t)(t - 1) * BT + blockIdx.y * 16) * HD);
#pragma unroll
            for (int q = 0; q < 8; q++) {
                int p = tid + q * 128;          // 0..1023 float4s
                float4 v = __ldcg(hp + p);
                int rr = p >> 6;                // batch row 0..15
                int cc = (p & 63) * 4;          // col 0..252
                *(float4*)&hs[rr * 260 + cc] = v;
            }
            __syncthreads();

            // ---- 3x256 dot from smem ----
            const float* hrow = &hs[bl * 260];
            float4 vr = {0,0,0,0}, vz = {0,0,0,0}, vn = {0,0,0,0};
#pragma unroll 16
            for (int i = 0; i < 64; i++) {
                float4 hv = *(const float4*)&hrow[i * 4];
                float4 w1 = *(const float4*)&wr[i * 4];
                float4 w2 = *(const float4*)&wz[i * 4];
                float4 w3 = *(const float4*)&wn[i * 4];
                vr.x += hv.x * w1.x; vr.y += hv.y * w1.y;
                vr.z += hv.z * w1.z; vr.w += hv.w * w1.w;
                vz.x += hv.x * w2.x; vz.y += hv.y * w2.y;
                vz.z += hv.z * w2.z; vz.w += hv.w * w2.w;
                vn.x += hv.x * w3.x; vn.y += hv.y * w3.y;
                vn.z += hv.z * w3.z; vn.w += hv.w * w3.w;
            }
            accr = (vr.x + vr.y) + (vr.z + vr.w);
            accz = (vz.x + vz.y) + (vz.z + vz.w);
            accn = (vn.x + vn.y) + (vn.z + vn.w);
            hprev = hs[bl * 260 + k];
        }

        float r = 1.0f / (1.0f + expf(-(gr + br_ + accr)));
        float z = 1.0f / (1.0f + expf(-(gz + bz_ + accz)));
        float n = tanhf(gn + bn_ + r * accn);
        float hn = (1.0f - z) * n + z * hprev;

        __stcg(&h_all[((size_t)t * BT + b) * HD + k], hn);

        // ---- release h[t] ----
        __threadfence();          // order h store before the arrive
        __syncthreads();          // whole CTA has stored (and finished with hs)
        if (tid == 0) atomicAdd(bar, 1u);
    }
}

// ---------------- fused heads + output --------------------------------------
__global__ void __launch_bounds__(256)
k_head(const float* __restrict__ h2, const float* __restrict__ Hn,
       const float* __restrict__ l1W, const float* __restrict__ l1b,
       const float* __restrict__ l2W, const float* __restrict__ l2b,
       const float* __restrict__ l3W, const float* __restrict__ l3b,
       float* __restrict__ out)
{
    int w = threadIdx.x >> 5, lane = threadIdx.x & 31;
    int r = blockIdx.x * 8 + w;              // row = b*512 + n
    int b = r >> 9, n = r & 511;
    const float* h2row = h2 + ((size_t)n * BT + b) * HD;
    const float* hnrow = Hn + (size_t)r * HD;
    float s1 = 0.f, s2 = 0.f;
#pragma unroll
    for (int j = 0; j < 8; j++) {
        int kk = lane + j * 32;
        s2 += h2row[kk] * l2W[kk];
        float hv = hnrow[kk];
        s1 += fmaxf(hv, 0.f) * l1W[kk];
    }
#pragma unroll
    for (int o = 16; o > 0; o >>= 1) {
        s1 += __shfl_xor_sync(0xFFFFFFFFu, s1, o);
        s2 += __shfl_xor_sync(0xFFFFFFFFu, s2, o);
    }
    float g  = s2 + l2b[0];
    float hh = s1 + l1b[0];
    if (lane < OUTD)
        out[(size_t)r * OUTD + lane] = g * l3W[lane] + hh * l3W[OUTD + lane] + l3b[lane];
}

// ---------------- host orchestration ----------------------------------------
extern "C" void kernel_launch(void* const* d_in, const int* in_sizes, int n_in,
                              void* d_out, int out_size)
{
    (void)in_sizes; (void)n_in; (void)out_size;

    const float* x    = (const float*)d_in[0];
    const int*   ei   = (const int*)  d_in[1];
    const float* ew   = (const float*)d_in[2];
    const float* Wz   = (const float*)d_in[3];
    const float* bz   = (const float*)d_in[4];
    const float* lzW  = (const float*)d_in[5];
    const float* lzb  = (const float*)d_in[6];
    // d_in[7..10] = Wr, br, lr_W, lr_b : dead (Hst = 0 kills the R branch)
    const float* Wh   = (const float*)d_in[11];
    const float* bh   = (const float*)d_in[12];
    const float* lhW  = (const float*)d_in[13];
    const float* lhb  = (const float*)d_in[14];
    const float* Wih0 = (const float*)d_in[15];
    const float* Whh0 = (const float*)d_in[16];
    const float* bih0 = (const float*)d_in[17];
    const float* bhh0 = (const float*)d_in[18];
    const float* Wih1 = (const float*)d_in[19];
    const float* Whh1 = (const float*)d_in[20];
    const float* bih1 = (const float*)d_in[21];
    const float* bhh1 = (const float*)d_in[22];
    const float* l1W  = (const float*)d_in[23];
    const float* l1b  = (const float*)d_in[24];
    const float* l2W  = (const float*)d_in[25];
    const float* l2b  = (const float*)d_in[26];
    const float* l3W  = (const float*)d_in[27];
    const float* l3b  = (const float*)d_in[28];
    float* out = (float*)d_out;

    void *p_xs, *p_agg, *p_gi0, *p_gi1, *p_h1, *p_h2,
         *p_cz, *p_ch, *p_Z, *p_Hn, *p_WT0, *p_WT1, *p_b0, *p_b1;
    cudaGetSymbolAddress(&p_xs,  g_xs);
    cudaGetSymbolAddress(&p_agg, g_agg);
    cudaGetSymbolAddress(&p_gi0, g_gi0);
    cudaGetSymbolAddress(&p_gi1, g_gi1);
    cudaGetSymbolAddress(&p_h1,  g_h1);
    cudaGetSymbolAddress(&p_h2,  g_h2);
    cudaGetSymbolAddress(&p_cz,  g_cz);
    cudaGetSymbolAddress(&p_ch,  g_ch);
    cudaGetSymbolAddress(&p_Z,   g_Z);
    cudaGetSymbolAddress(&p_Hn,  g_Hn);
    cudaGetSymbolAddress(&p_WT0, g_WT0);
    cudaGetSymbolAddress(&p_WT1, g_WT1);
    cudaGetSymbolAddress(&p_b0,  g_bar0);
    cudaGetSymbolAddress(&p_b1,  g_bar1);

    // ---- graph structure (deterministic CSR; zero float atomics) ----
    k_zero<<<3, 256>>>();
    k_count<<<32, 256>>>(ei);
    k_scan<<<1, 32>>>();
    k_fill<<<32, 256>>>(ei);
    k_sortdeg<<<2, 256>>>(ew);
    k_norm<<<32, 256>>>(ei, ew);

    // ---- layout prep ----
    k_xs<<<dim3(NSEQ, BT), CIND>>>(x, (float*)p_xs);
    k_transpose<<<(G3 * CIND + 255) / 256, 256>>>(Wih0, (float*)p_WT0, G3, CIND);
    k_transpose<<<(G3 * HD + 255) / 256, 256>>>(Wih1, (float*)p_WT1, G3, HD);
    k_agg<<<dim3(NSEQ, BT), CIND>>>(x, (float*)p_agg);

    // ---- parallel GEMMs ----
    // gi0 = xs @ Wih0^T + bih0   [32768,128] x [128,768]
    gemm128<<<dim3(G3 / 128, ROWS / 128), 256>>>(
        (const float*)p_xs, (const float*)p_WT0, bih0, (float*)p_gi0,
        G3, CIND, 0, nullptr);
    // cz = agg @ Wz + bz ; ch = agg @ Wh + bh     (A(XW) = (AX)W)
    gemm128<<<dim3(HD / 128, ROWS / 128), 256>>>(
        (const float*)p_agg, Wz, bz, (float*)p_cz, HD, CIND, 0, nullptr);
    gemm128<<<dim3(HD / 128, ROWS / 128), 256>>>(
        (const float*)p_agg, Wh, bh, (float*)p_ch, HD, CIND, 0, nullptr);
    // Z = sigmoid(cz @ lzW[0:256] + lzb)
    gemm128<<<dim3(HD / 128, ROWS / 128), 256>>>(
        (const float*)p_cz, lzW, lzb, (float*)p_Z, HD, HD, 1, nullptr);
    // Hn = (1-Z) * tanh(ch @ lhW[0:256] + lhb)
    gemm128<<<dim3(HD / 128, ROWS / 128), 256>>>(
        (const float*)p_ch, lhW, lhb, (float*)p_Hn, HD, HD, 3, (const float*)p_Z);

    // ---- GRU layer 0 scan (single persistent kernel, 512 steps) ----
    gru_scan<<<dim3(32, 4), 128>>>((float*)p_h1, (const float*)p_gi0,
                                   Whh0, bhh0, (unsigned*)p_b0);

    // gi1 = h1 @ Wih1^T + bih1   [32768,256] x [256,768]
    gemm128<<<dim3(G3 / 128, ROWS / 128), 256>>>(
        (const float*)p_h1, (const float*)p_WT1, bih1, (float*)p_gi1,
        G3, HD, 0, nullptr);

    // ---- GRU layer 1 scan ----
    gru_scan<<<dim3(32, 4), 128>>>((float*)p_h2, (const float*)p_gi1,
                                   Whh1, bhh1, (unsigned*)p_b1);

    // ---- fused heads -> out ----
    k_head<<<ROWS / 8, 256>>>((const float*)p_h2, (const float*)p_Hn,
                              l1W, l1b, l2W, l2b, l3W, l3b, out);
}